// round 1
// baseline (speedup 1.0000x reference)
#include <cuda_runtime.h>

// Encoder_82910048682485 — binary-tree bottom-up encoder, fp32 baseline.
//
// Structure exploited: children of the contiguous parent range [p0, p0+n) are
// the contiguous node range [2*p0+1, 2*p0+2n], i.e. each level's input X
// ([n, 256]) is just a flat slab of the output buffer, and its output is the
// slab right before it. So the whole reference = leaf GEMM + 18 fused MLPs on
// contiguous memory.

static __forceinline__ __device__ float lrelu(float v) {
    return v > 0.0f ? v : 0.01f * v;
}

constexpr int DEPTH = 18;
constexpr int SM_FLOATS = 64 * 260 + 64 * 260 + 256 * 64;   // sX + sH + sW
constexpr size_t SMEM_BYTES = (size_t)SM_FLOATS * 4;        // 198656 B

// Fused 2-layer MLP for one tree level.
//   X: [n, 256] contiguous children slab
//   Y: [n, 128] parent slab
// Block: 256 threads, 64-row tile. Layer1 h kept in smem, never hits HBM.
__global__ void __launch_bounds__(256, 1) mlp_level_kernel(
    const float* __restrict__ X,
    float* __restrict__ Y,
    const float* __restrict__ W1,   // [256,256] row-major
    const float* __restrict__ b1,   // [256]
    const float* __restrict__ W2,   // [256,128] row-major
    const float* __restrict__ b2,   // [128]
    int n)
{
    extern __shared__ float smem[];
    float* sX = smem;                 // [64][260]  (stride 260: 16B-aligned rows, conflict-free column reads)
    float* sH = smem + 64 * 260;      // [64][260]
    float* sW = smem + 2 * 64 * 260;  // [256][64]

    const int tid = threadIdx.x;
    const int tx = tid & 15;          // 16 col-groups of 4
    const int ty = tid >> 4;          // 16 row-groups of 4
    const int row0 = blockIdx.x * 64;
    // Thread owns rows row0+ty*4 .. +3. If none exist (tiny levels), skip
    // compute but still participate in loads + barriers.
    const bool active = (row0 + ty * 4) < n;

    // ---- load X tile [64, 256] (zero-fill rows >= n) ----
    for (int idx = tid; idx < 64 * 64; idx += 256) {
        int r = idx >> 6, c4 = idx & 63;
        float4 v = make_float4(0.f, 0.f, 0.f, 0.f);
        if (row0 + r < n)
            v = reinterpret_cast<const float4*>(X)[(size_t)(row0 + r) * 64 + c4];
        *reinterpret_cast<float4*>(&sX[r * 260 + c4 * 4]) = v;
    }

    // ---- layer 1: h = lrelu(X @ W1 + b1), 4 chunks of 64 output cols ----
    for (int nc = 0; nc < 4; ++nc) {
        __syncthreads();
        for (int idx = tid; idx < 256 * 16; idx += 256) {
            int k = idx >> 4, j4 = idx & 15;
            *reinterpret_cast<float4*>(&sW[k * 64 + j4 * 4]) =
                reinterpret_cast<const float4*>(W1 + k * 256 + nc * 64)[j4];
        }
        __syncthreads();
        if (active) {
            float4 bb = *reinterpret_cast<const float4*>(b1 + nc * 64 + tx * 4);
            float acc[4][4];
            #pragma unroll
            for (int i = 0; i < 4; ++i) {
                acc[i][0] = bb.x; acc[i][1] = bb.y; acc[i][2] = bb.z; acc[i][3] = bb.w;
            }
            #pragma unroll 8
            for (int k = 0; k < 256; ++k) {
                float4 b = *reinterpret_cast<float4*>(&sW[k * 64 + tx * 4]);
                #pragma unroll
                for (int i = 0; i < 4; ++i) {
                    float a = sX[(ty * 4 + i) * 260 + k];
                    acc[i][0] = fmaf(a, b.x, acc[i][0]);
                    acc[i][1] = fmaf(a, b.y, acc[i][1]);
                    acc[i][2] = fmaf(a, b.z, acc[i][2]);
                    acc[i][3] = fmaf(a, b.w, acc[i][3]);
                }
            }
            #pragma unroll
            for (int i = 0; i < 4; ++i) {
                float4 o;
                o.x = lrelu(acc[i][0]); o.y = lrelu(acc[i][1]);
                o.z = lrelu(acc[i][2]); o.w = lrelu(acc[i][3]);
                *reinterpret_cast<float4*>(&sH[(ty * 4 + i) * 260 + nc * 64 + tx * 4]) = o;
            }
        }
    }

    // ---- layer 2: out = lrelu(h @ W2 + b2), 2 chunks of 64 output cols ----
    for (int oc = 0; oc < 2; ++oc) {
        __syncthreads();
        for (int idx = tid; idx < 256 * 16; idx += 256) {
            int k = idx >> 4, j4 = idx & 15;
            *reinterpret_cast<float4*>(&sW[k * 64 + j4 * 4]) =
                reinterpret_cast<const float4*>(W2 + k * 128 + oc * 64)[j4];
        }
        __syncthreads();
        if (active) {
            float4 bb = *reinterpret_cast<const float4*>(b2 + oc * 64 + tx * 4);
            float acc[4][4];
            #pragma unroll
            for (int i = 0; i < 4; ++i) {
                acc[i][0] = bb.x; acc[i][1] = bb.y; acc[i][2] = bb.z; acc[i][3] = bb.w;
            }
            #pragma unroll 8
            for (int k = 0; k < 256; ++k) {
                float4 b = *reinterpret_cast<float4*>(&sW[k * 64 + tx * 4]);
                #pragma unroll
                for (int i = 0; i < 4; ++i) {
                    float a = sH[(ty * 4 + i) * 260 + k];
                    acc[i][0] = fmaf(a, b.x, acc[i][0]);
                    acc[i][1] = fmaf(a, b.y, acc[i][1]);
                    acc[i][2] = fmaf(a, b.z, acc[i][2]);
                    acc[i][3] = fmaf(a, b.w, acc[i][3]);
                }
            }
            #pragma unroll
            for (int i = 0; i < 4; ++i) {
                int r = row0 + ty * 4 + i;
                if (r < n) {
                    float4 o;
                    o.x = lrelu(acc[i][0]); o.y = lrelu(acc[i][1]);
                    o.z = lrelu(acc[i][2]); o.w = lrelu(acc[i][3]);
                    *reinterpret_cast<float4*>(Y + (size_t)r * 128 + oc * 64 + tx * 4) = o;
                }
            }
        }
    }
}

// Leaf embedder: Y[i] = lrelu(L[i, :32] @ We + be). 64 rows/block, K=32.
// N_LEAVES is a multiple of 64 — no guards needed.
__global__ void __launch_bounds__(256, 1) leaf_kernel(
    const float* __restrict__ L,    // [N_LEAVES, 32]
    const float* __restrict__ We,   // [32, 128]
    const float* __restrict__ be,   // [128]
    float* __restrict__ Y)          // [N_LEAVES, 128] (pre-offset to leaf slab)
{
    __shared__ float sL[64 * 36];
    __shared__ float sW[32 * 128];

    const int tid = threadIdx.x;
    const int tx = tid & 15;        // 16 col-groups of 8
    const int ty = tid >> 4;        // 16 row-groups of 4
    const size_t row0 = (size_t)blockIdx.x * 64;

    for (int idx = tid; idx < 512; idx += 256) {
        int r = idx >> 3, c4 = idx & 7;
        float4 v = reinterpret_cast<const float4*>(L + (row0 + r) * 32)[c4];
        *reinterpret_cast<float4*>(&sL[r * 36 + c4 * 4]) = v;
    }
    for (int idx = tid; idx < 1024; idx += 256)
        reinterpret_cast<float4*>(sW)[idx] = reinterpret_cast<const float4*>(We)[idx];
    __syncthreads();

    float acc[4][8];
    float4 e0 = *reinterpret_cast<const float4*>(be + tx * 8);
    float4 e1 = *reinterpret_cast<const float4*>(be + tx * 8 + 4);
    #pragma unroll
    for (int i = 0; i < 4; ++i) {
        acc[i][0] = e0.x; acc[i][1] = e0.y; acc[i][2] = e0.z; acc[i][3] = e0.w;
        acc[i][4] = e1.x; acc[i][5] = e1.y; acc[i][6] = e1.z; acc[i][7] = e1.w;
    }
    #pragma unroll 8
    for (int k = 0; k < 32; ++k) {
        float4 b0 = *reinterpret_cast<float4*>(&sW[k * 128 + tx * 8]);
        float4 b1 = *reinterpret_cast<float4*>(&sW[k * 128 + tx * 8 + 4]);
        #pragma unroll
        for (int i = 0; i < 4; ++i) {
            float a = sL[(ty * 4 + i) * 36 + k];
            acc[i][0] = fmaf(a, b0.x, acc[i][0]);
            acc[i][1] = fmaf(a, b0.y, acc[i][1]);
            acc[i][2] = fmaf(a, b0.z, acc[i][2]);
            acc[i][3] = fmaf(a, b0.w, acc[i][3]);
            acc[i][4] = fmaf(a, b1.x, acc[i][4]);
            acc[i][5] = fmaf(a, b1.y, acc[i][5]);
            acc[i][6] = fmaf(a, b1.z, acc[i][6]);
            acc[i][7] = fmaf(a, b1.w, acc[i][7]);
        }
    }
    #pragma unroll
    for (int i = 0; i < 4; ++i) {
        size_t r = row0 + ty * 4 + i;
        float4 o0, o1;
        o0.x = lrelu(acc[i][0]); o0.y = lrelu(acc[i][1]);
        o0.z = lrelu(acc[i][2]); o0.w = lrelu(acc[i][3]);
        o1.x = lrelu(acc[i][4]); o1.y = lrelu(acc[i][5]);
        o1.z = lrelu(acc[i][6]); o1.w = lrelu(acc[i][7]);
        reinterpret_cast<float4*>(Y + r * 128 + tx * 8)[0] = o0;
        reinterpret_cast<float4*>(Y + r * 128 + tx * 8)[1] = o1;
    }
}

extern "C" void kernel_launch(void* const* d_in, const int* in_sizes, int n_in,
                              void* d_out, int out_size)
{
    const float* leaf = (const float*)d_in[0];
    const float* We   = (const float*)d_in[1];
    const float* be   = (const float*)d_in[2];
    const float* W1   = (const float*)d_in[3];
    const float* b1   = (const float*)d_in[4];
    const float* W2   = (const float*)d_in[5];
    const float* b2   = (const float*)d_in[6];
    float* out = (float*)d_out;

    // Opt-in to >48KB dynamic smem (host attribute set, not a stream op — capture-safe).
    cudaFuncSetAttribute(mlp_level_kernel,
                         cudaFuncAttributeMaxDynamicSharedMemorySize, (int)SMEM_BYTES);

    const size_t leaf_start = (size_t)(1u << DEPTH) - 1;   // 262143
    leaf_kernel<<<(1 << DEPTH) / 64, 256>>>(leaf, We, be, out + leaf_start * 128);

    for (int l = DEPTH - 1; l >= 0; --l) {
        const int n = 1 << l;
        const size_t p0 = (size_t)(1u << l) - 1;
        const float* X = out + (2 * p0 + 1) * 128;   // children slab = level l+1 slab
        float* Y = out + p0 * 128;                   // parent slab
        const int grid = (n + 63) / 64;
        mlp_level_kernel<<<grid, 256, SMEM_BYTES>>>(X, Y, W1, b1, W2, b2, n);
    }
}